// round 8
// baseline (speedup 1.0000x reference)
#include <cuda_runtime.h>
#include <cuda_fp16.h>
#include <cstdint>

// Shapes (fixed by the problem)
#define Bq 2
#define Nq 2048
#define Mq 32
#define Hq 8
#define Dq 64
#define Eq 512
#define Fq 512
#define Pq 6

// ---------------------------------------------------------------------------
// Scratch (graph-capture rules forbid cudaMalloc)
// ---------------------------------------------------------------------------
__device__ float  g_Q [Bq * Nq * Eq];     // fp32 Q projections
__device__ __half g_Kh[Bq * Nq * Eq];     // fp16 K projections (gather + kb)
__device__ __half g_x16[2][Bq * Nq * Fq]; // fp16 inputs: [0]=qf, [1]=kf
__device__ __half g_w16[2][Eq * Fq];      // fp16 transposed weights [n][k]

// ---------------------------------------------------------------------------
// helpers
// ---------------------------------------------------------------------------
__device__ __forceinline__ uint32_t smem_u32(const void* p) {
    uint32_t a;
    asm("{ .reg .u64 t; cvta.to.shared.u64 t, %1; cvt.u32.u64 %0, t; }" : "=r"(a) : "l"(p));
    return a;
}
__device__ __forceinline__ void cpasync16(uint32_t s, const void* g) {
    asm volatile("cp.async.cg.shared.global [%0], [%1], 16;" :: "r"(s), "l"(g));
}
__device__ __forceinline__ void ldsm_x4(uint32_t& r0, uint32_t& r1, uint32_t& r2, uint32_t& r3,
                                        uint32_t addr) {
    asm volatile("ldmatrix.sync.aligned.m8n8.x4.shared.b16 {%0,%1,%2,%3}, [%4];"
                 : "=r"(r0), "=r"(r1), "=r"(r2), "=r"(r3) : "r"(addr));
}
__device__ __forceinline__ void mma_f16(float* c, const uint32_t* a, uint32_t b0, uint32_t b1) {
    asm volatile(
        "mma.sync.aligned.m16n8k16.row.col.f32.f16.f16.f32 "
        "{%0,%1,%2,%3}, {%4,%5,%6,%7}, {%8,%9}, {%0,%1,%2,%3};"
        : "+f"(c[0]), "+f"(c[1]), "+f"(c[2]), "+f"(c[3])
        : "r"(a[0]), "r"(a[1]), "r"(a[2]), "r"(a[3]), "r"(b0), "r"(b1));
}
__device__ __forceinline__ void h8_to_f(const uint4& kv, float* f) {
    const __half2* hp = reinterpret_cast<const __half2*>(&kv);
#pragma unroll
    for (int i = 0; i < 4; i++) {
        float2 t = __half22float2(hp[i]);
        f[2 * i] = t.x;
        f[2 * i + 1] = t.y;
    }
}

// ---------------------------------------------------------------------------
// prep: blocks 0..1023 convert X fp32->fp16 (2 float4 per thread, MLP 2);
// blocks 1024..1279 transpose+convert W. z=0 -> (qf,Wq); z=1 -> (kf,Wk).
// ---------------------------------------------------------------------------
__global__ __launch_bounds__(256) void prep_kernel(
    const float* __restrict__ qf, const float* __restrict__ kf,
    const float* __restrict__ Wq_, const float* __restrict__ Wk_)
{
    __shared__ float tile[32][33];
    const int z = blockIdx.z;
    const int tid = threadIdx.x;

    if (blockIdx.x < 1024) {
        const float* in = z ? kf : qf;
        __half* o = g_x16[z];
        const int f0 = blockIdx.x * 512 + tid;
        float4 x0 = ((const float4*)in)[f0];
        float4 x1 = ((const float4*)in)[f0 + 256];
        __half2 a0 = __floats2half2_rn(x0.x, x0.y);
        __half2 a1 = __floats2half2_rn(x0.z, x0.w);
        __half2 b0 = __floats2half2_rn(x1.x, x1.y);
        __half2 b1 = __floats2half2_rn(x1.z, x1.w);
        ((uint2*)o)[f0]       = make_uint2(*(uint32_t*)&a0, *(uint32_t*)&a1);
        ((uint2*)o)[f0 + 256] = make_uint2(*(uint32_t*)&b0, *(uint32_t*)&b1);
    } else {
        const int bx = blockIdx.x - 1024;               // 0..255
        const float* in = z ? Wk_ : Wq_;
        __half* o = g_w16[z];
        const int tx = tid & 31, ty = tid >> 5;         // 32 x 8
        const int n0 = (bx & 15) * 32, k0 = (bx >> 4) * 32;
#pragma unroll
        for (int j = 0; j < 4; j++)
            tile[ty + j * 8][tx] = in[(size_t)(k0 + ty + j * 8) * Eq + n0 + tx];
        __syncthreads();
#pragma unroll
        for (int j = 0; j < 4; j++)
            o[(size_t)(n0 + ty + j * 8) * Fq + k0 + tx] = __float2half_rn(tile[tx][ty + j * 8]);
    }
}

// ---------------------------------------------------------------------------
// GEMM via single-pass fp16 mma.sync: C[4096,512] = X @ W. (unchanged)
// ---------------------------------------------------------------------------
#define KC 32
#define LDE 40
#define TILE_B (128 * LDE * 2)
#define BUF_B (2 * TILE_B)
#define GEMM_SMEM (2 * BUF_B)        // 40960

__global__ __launch_bounds__(256, 2) void gemm_tc_kernel()
{
    extern __shared__ char smem[];
    const uint32_t sbase = smem_u32(smem);
    const int tid = threadIdx.x;
    const int wid = tid >> 5;
    const int lane = tid & 31;
    const int z = blockIdx.z;
    const int rowBase = blockIdx.y * 128;
    const int colBase = blockIdx.x * 128;

    const __half* X = g_x16[z];
    const __half* W = g_w16[z];

    const int wm = (wid >> 2) * 64;
    const int wn = (wid & 3) * 32;

    const int r0a = tid >> 2, s0 = (tid & 3) * 8;
    const int r1a = (tid + 256) >> 2;

    float acc[4][4][4];
#pragma unroll
    for (int mt = 0; mt < 4; mt++)
#pragma unroll
        for (int nt = 0; nt < 4; nt++)
#pragma unroll
            for (int i = 0; i < 4; i++) acc[mt][nt][i] = 0.f;

    auto stage = [&](int buf, int kt) {
        const uint32_t sb = sbase + buf * BUF_B;
#pragma unroll
        for (int t = 0; t < 2; t++) {
            const int row = t ? r1a : r0a;
            const uint32_t so = (uint32_t)(row * LDE + s0) * 2;
            cpasync16(sb + so,          X + (size_t)(rowBase + row) * Fq + kt + s0);
            cpasync16(sb + TILE_B + so, W + (size_t)(colBase + row) * Fq + kt + s0);
        }
        asm volatile("cp.async.commit_group;");
    };

    const int lj = lane >> 3, lr = lane & 7;
    const int arow = (lj & 1) * 8 + lr;
    const int acol = (lj >> 1) * 8;
    const int brow = (lj >> 1) * 8 + lr;
    const int bcol = (lj & 1) * 8;

    stage(0, 0);

    const int NCHUNK = Fq / KC;               // 16
    for (int c = 0; c < NCHUNK; c++) {
        if (c + 1 < NCHUNK) stage((c + 1) & 1, (c + 1) * KC);
        if (c + 1 < NCHUNK) asm volatile("cp.async.wait_group 1;");
        else                asm volatile("cp.async.wait_group 0;");
        __syncthreads();

        const uint32_t sb = sbase + (c & 1) * BUF_B;
#pragma unroll
        for (int ks = 0; ks < 2; ks++) {
            const int kof = ks * 16;
            uint32_t a[4][4], bfr[2][4];
#pragma unroll
            for (int mt = 0; mt < 4; mt++)
                ldsm_x4(a[mt][0], a[mt][1], a[mt][2], a[mt][3],
                        sb + (uint32_t)((wm + mt * 16 + arow) * LDE + kof + acol) * 2);
#pragma unroll
            for (int np = 0; np < 2; np++)
                ldsm_x4(bfr[np][0], bfr[np][1], bfr[np][2], bfr[np][3],
                        sb + TILE_B + (uint32_t)((wn + np * 16 + brow) * LDE + kof + bcol) * 2);
#pragma unroll
            for (int mt = 0; mt < 4; mt++)
#pragma unroll
                for (int nt = 0; nt < 4; nt++)
                    mma_f16(acc[mt][nt], a[mt],
                            bfr[nt >> 1][(nt & 1) * 2], bfr[nt >> 1][(nt & 1) * 2 + 1]);
        }
        __syncthreads();
    }

    const int g = lane >> 2, tg = lane & 3;
    if (z == 0) {
#pragma unroll
        for (int mt = 0; mt < 4; mt++)
#pragma unroll
            for (int nt = 0; nt < 4; nt++) {
                const int row = rowBase + wm + mt * 16 + g;
                const int col = colBase + wn + nt * 8 + 2 * tg;
                *(float2*)(g_Q + (size_t)row * Eq + col) =
                    make_float2(acc[mt][nt][0], acc[mt][nt][1]);
                *(float2*)(g_Q + (size_t)(row + 8) * Eq + col) =
                    make_float2(acc[mt][nt][2], acc[mt][nt][3]);
            }
    } else {
#pragma unroll
        for (int mt = 0; mt < 4; mt++)
#pragma unroll
            for (int nt = 0; nt < 4; nt++) {
                const int row = rowBase + wm + mt * 16 + g;
                const int col = colBase + wn + nt * 8 + 2 * tg;
                *(__half2*)(g_Kh + (size_t)row * Eq + col) =
                    __floats2half2_rn(acc[mt][nt][0], acc[mt][nt][1]);
                *(__half2*)(g_Kh + (size_t)(row + 8) * Eq + col) =
                    __floats2half2_rn(acc[mt][nt][2], acc[mt][nt][3]);
            }
    }
}

// ---------------------------------------------------------------------------
// Fused epilogue v3: one CTA (256 thr, 8 warps) per token (b,n).
// K gather goes through cp.async -> smem (32 rows x 1KB = 32KB): no gathered
// data in registers, async engine absorbs L2 latency, proj/kb overlap the
// copy. Content reads conflict-free LDS.128 from the staged tile.
// Element e = c*256 + l*8 + j -> head 4c + (l>>3); reduce over 8-lane groups.
// ---------------------------------------------------------------------------
__device__ __forceinline__ float red16(float s) {
    s += __shfl_xor_sync(0xffffffffu, s, 1);
    s += __shfl_xor_sync(0xffffffffu, s, 2);
    s += __shfl_xor_sync(0xffffffffu, s, 4);
    s += __shfl_xor_sync(0xffffffffu, s, 8);
    return s;
}
__device__ __forceinline__ float red8(float s) {
    s += __shfl_xor_sync(0xffffffffu, s, 1);
    s += __shfl_xor_sync(0xffffffffu, s, 2);
    s += __shfl_xor_sync(0xffffffffu, s, 4);
    return s;
}

struct FuseSmem {
    __half ktile[Mq][Eq];     // 32 KB staged gathered K rows
    float proj[Pq][Hq];
    float kb[Hq];
    float cont[Mq][Hq];
};

__global__ __launch_bounds__(256) void fuse_kernel(
    const float* __restrict__ pl,     // (B,N,M,P)
    const int*   __restrict__ nbhd,   // (B,N,M)
    const float* __restrict__ Wl,     // (P,E)
    const float* __restrict__ u,      // 512 contiguous
    const float* __restrict__ v,      // 512 contiguous
    float*       __restrict__ out)    // (B,N,M,H)
{
    extern __shared__ char smraw[];
    FuseSmem* sm = (FuseSmem*)smraw;
    const uint32_t sbase = smem_u32(smraw);

    const int bn = blockIdx.x;        // 0..4095
    const int b  = bn >> 11;
    const int tid = threadIdx.x;
    const int w = tid >> 5;
    const int l = tid & 31;

    // ---- phase 1: async gather of 32 K rows into smem ----
    const __half* Kbase = g_Kh + (size_t)b * Nq * Eq;
    const int* nbp = nbhd + (size_t)bn * Mq;
#pragma unroll
    for (int i = 0; i < 8; i++) {
        const int seg_id = i * 256 + tid;         // 0..2047
        const int row = seg_id >> 6;              // 0..31
        const int seg = seg_id & 63;              // 16B segment within row
        cpasync16(sbase + (uint32_t)(row * Eq + seg * 8) * 2,
                  Kbase + (size_t)nbp[row] * Eq + seg * 8);
    }
    asm volatile("cp.async.commit_group;");

    // ---- phase 2 (overlaps gather): proj / kb ----
    if (w < 6) {
        const float* Qg = g_Q + (size_t)bn * Eq;
        const float* wlr = Wl + w * Eq;
        const int hsub = l >> 4;
#pragma unroll
        for (int c = 0; c < 4; c++) {
            float4 qc = *(const float4*)(Qg + c * 128 + l * 4);
            float4 wv = *(const float4*)(wlr + c * 128 + l * 4);
            float4 vf = *(const float4*)(v + c * 128 + l * 4);
            float s = 0.f;
            s = fmaf(wv.x, qc.x + vf.x, s);
            s = fmaf(wv.y, qc.y + vf.y, s);
            s = fmaf(wv.z, qc.z + vf.z, s);
            s = fmaf(wv.w, qc.w + vf.w, s);
            s = red16(s);
            if ((l & 15) == 0) sm->proj[w][2 * c + hsub] = s;
        }
    } else if (w == 6) {
        const __half* Kg = g_Kh + (size_t)bn * Eq;
#pragma unroll
        for (int c = 0; c < 2; c++) {
            uint4 kk = *(const uint4*)(Kg + c * 256 + l * 8);
            float kf[8];
            h8_to_f(kk, kf);
            float4 u0 = *(const float4*)(u + c * 256 + l * 8);
            float4 u1 = *(const float4*)(u + c * 256 + l * 8 + 4);
            float s = 0.f;
            s = fmaf(kf[0], u0.x, s); s = fmaf(kf[1], u0.y, s);
            s = fmaf(kf[2], u0.z, s); s = fmaf(kf[3], u0.w, s);
            s = fmaf(kf[4], u1.x, s); s = fmaf(kf[5], u1.y, s);
            s = fmaf(kf[6], u1.z, s); s = fmaf(kf[7], u1.w, s);
            s = red8(s);
            if ((l & 7) == 0) sm->kb[c * 4 + (l >> 3)] = s;
        }
    }

    // Q slice (fp32) matching fp16 chunk mapping
    float q16[16];
#pragma unroll
    for (int c = 0; c < 2; c++) {
        float4 a = *(const float4*)(g_Q + (size_t)bn * Eq + c * 256 + l * 8);
        float4 bb = *(const float4*)(g_Q + (size_t)bn * Eq + c * 256 + l * 8 + 4);
        q16[c * 8 + 0] = a.x;  q16[c * 8 + 1] = a.y;
        q16[c * 8 + 2] = a.z;  q16[c * 8 + 3] = a.w;
        q16[c * 8 + 4] = bb.x; q16[c * 8 + 5] = bb.y;
        q16[c * 8 + 6] = bb.z; q16[c * 8 + 7] = bb.w;
    }

    // ---- phase 3: content from staged smem ----
    asm volatile("cp.async.wait_group 0;");
    __syncthreads();

#pragma unroll
    for (int mi = 0; mi < 4; mi++) {
        const int m = w + mi * 8;
#pragma unroll
        for (int c = 0; c < 2; c++) {
            uint4 kk = *(const uint4*)&sm->ktile[m][c * 256 + l * 8];
            float kf[8];
            h8_to_f(kk, kf);
            float s = 0.f;
#pragma unroll
            for (int j = 0; j < 8; j++) s = fmaf(kf[j], q16[c * 8 + j], s);
            s = red8(s);
            if ((l & 7) == 0) sm->cont[m][c * 4 + (l >> 3)] = s;
        }
    }
    __syncthreads();

    // ---- phase 4: combine ----
    const int m = tid >> 3;
    const int h = tid & 7;
    const float* plp = pl + ((size_t)bn * Mq + m) * Pq;
    float p = 0.f;
#pragma unroll
    for (int pp = 0; pp < Pq; pp++) p = fmaf(plp[pp], sm->proj[pp][h], p);
    out[((size_t)bn * Mq + m) * Hq + h] = (sm->cont[m][h] + p + sm->kb[h]) * 0.125f;
}

// ---------------------------------------------------------------------------
// Launch
// Inputs: 0 pairwise_locations, 1 mask (unused), 2 query_features,
// 3 key_features, 4 nbhd_idx, 5 Wq, 6 Wk, 7 Wl, 8 u, 9 v
// ---------------------------------------------------------------------------
extern "C" void kernel_launch(void* const* d_in, const int* in_sizes, int n_in,
                              void* d_out, int out_size)
{
    const float* pl   = (const float*)d_in[0];
    const float* qf   = (const float*)d_in[2];
    const float* kf   = (const float*)d_in[3];
    const int*   nb   = (const int*)  d_in[4];
    const float* Wq_  = (const float*)d_in[5];
    const float* Wk_  = (const float*)d_in[6];
    const float* Wl   = (const float*)d_in[7];
    const float* u    = (const float*)d_in[8];
    const float* v    = (const float*)d_in[9];
    float*       out  = (float*)d_out;

    static int smem_set = 0;
    if (!smem_set) {
        cudaFuncSetAttribute(gemm_tc_kernel,
                             cudaFuncAttributeMaxDynamicSharedMemorySize, GEMM_SMEM);
        cudaFuncSetAttribute(fuse_kernel,
                             cudaFuncAttributeMaxDynamicSharedMemorySize, sizeof(FuseSmem));
        smem_set = 1;
    }

    prep_kernel<<<dim3(1280, 1, 2), 256>>>(qf, kf, Wq_, Wk_);
    gemm_tc_kernel<<<dim3(4, 32, 2), 256, GEMM_SMEM>>>();
    fuse_kernel<<<Bq * Nq, 256, sizeof(FuseSmem)>>>(pl, nb, Wl, u, v, out);
}

// round 9
// speedup vs baseline: 1.1597x; 1.1597x over previous
#include <cuda_runtime.h>
#include <cuda_fp16.h>
#include <cstdint>

// Shapes (fixed by the problem)
#define Bq 2
#define Nq 2048
#define Mq 32
#define Hq 8
#define Dq 64
#define Eq 512
#define Fq 512
#define Pq 6

// ---------------------------------------------------------------------------
// Scratch (graph-capture rules forbid cudaMalloc)
// ---------------------------------------------------------------------------
__device__ __half g_P[2][Bq * Nq * Eq];   // fp16 projections: [0]=Q, [1]=K
__device__ __half g_x16[2][Bq * Nq * Fq]; // fp16 inputs: [0]=qf, [1]=kf
__device__ __half g_w16[2][Eq * Fq];      // fp16 transposed weights [n][k]

// ---------------------------------------------------------------------------
// helpers
// ---------------------------------------------------------------------------
__device__ __forceinline__ uint32_t smem_u32(const void* p) {
    uint32_t a;
    asm("{ .reg .u64 t; cvta.to.shared.u64 t, %1; cvt.u32.u64 %0, t; }" : "=r"(a) : "l"(p));
    return a;
}
__device__ __forceinline__ void cpasync16(uint32_t s, const void* g) {
    asm volatile("cp.async.cg.shared.global [%0], [%1], 16;" :: "r"(s), "l"(g));
}
__device__ __forceinline__ void ldsm_x4(uint32_t& r0, uint32_t& r1, uint32_t& r2, uint32_t& r3,
                                        uint32_t addr) {
    asm volatile("ldmatrix.sync.aligned.m8n8.x4.shared.b16 {%0,%1,%2,%3}, [%4];"
                 : "=r"(r0), "=r"(r1), "=r"(r2), "=r"(r3) : "r"(addr));
}
__device__ __forceinline__ void mma_f16(float* c, const uint32_t* a, uint32_t b0, uint32_t b1) {
    asm volatile(
        "mma.sync.aligned.m16n8k16.row.col.f32.f16.f16.f32 "
        "{%0,%1,%2,%3}, {%4,%5,%6,%7}, {%8,%9}, {%0,%1,%2,%3};"
        : "+f"(c[0]), "+f"(c[1]), "+f"(c[2]), "+f"(c[3])
        : "r"(a[0]), "r"(a[1]), "r"(a[2]), "r"(a[3]), "r"(b0), "r"(b1));
}
__device__ __forceinline__ void h8_to_f(const uint4& kv, float* f) {
    const __half2* hp = reinterpret_cast<const __half2*>(&kv);
#pragma unroll
    for (int i = 0; i < 4; i++) {
        float2 t = __half22float2(hp[i]);
        f[2 * i] = t.x;
        f[2 * i + 1] = t.y;
    }
}
__device__ __forceinline__ float red16(float s) {
    s += __shfl_xor_sync(0xffffffffu, s, 1);
    s += __shfl_xor_sync(0xffffffffu, s, 2);
    s += __shfl_xor_sync(0xffffffffu, s, 4);
    s += __shfl_xor_sync(0xffffffffu, s, 8);
    return s;
}
__device__ __forceinline__ float red8(float s) {
    s += __shfl_xor_sync(0xffffffffu, s, 1);
    s += __shfl_xor_sync(0xffffffffu, s, 2);
    s += __shfl_xor_sync(0xffffffffu, s, 4);
    return s;
}

// ---------------------------------------------------------------------------
// prep: blocks 0..1023 convert X fp32->fp16 (2 float4/thread, MLP 2);
// blocks 1024..1279 transpose+convert W. z=0 -> (qf,Wq); z=1 -> (kf,Wk).
// ---------------------------------------------------------------------------
__global__ __launch_bounds__(256) void prep_kernel(
    const float* __restrict__ qf, const float* __restrict__ kf,
    const float* __restrict__ Wq_, const float* __restrict__ Wk_)
{
    __shared__ float tile[32][33];
    const int z = blockIdx.z;
    const int tid = threadIdx.x;

    if (blockIdx.x < 1024) {
        const float* in = z ? kf : qf;
        __half* o = g_x16[z];
        const int f0 = blockIdx.x * 512 + tid;
        float4 x0 = ((const float4*)in)[f0];
        float4 x1 = ((const float4*)in)[f0 + 256];
        __half2 a0 = __floats2half2_rn(x0.x, x0.y);
        __half2 a1 = __floats2half2_rn(x0.z, x0.w);
        __half2 b0 = __floats2half2_rn(x1.x, x1.y);
        __half2 b1 = __floats2half2_rn(x1.z, x1.w);
        ((uint2*)o)[f0]       = make_uint2(*(uint32_t*)&a0, *(uint32_t*)&a1);
        ((uint2*)o)[f0 + 256] = make_uint2(*(uint32_t*)&b0, *(uint32_t*)&b1);
    } else {
        const int bx = blockIdx.x - 1024;               // 0..255
        const float* in = z ? Wk_ : Wq_;
        __half* o = g_w16[z];
        const int tx = tid & 31, ty = tid >> 5;         // 32 x 8
        const int n0 = (bx & 15) * 32, k0 = (bx >> 4) * 32;
#pragma unroll
        for (int j = 0; j < 4; j++)
            tile[ty + j * 8][tx] = in[(size_t)(k0 + ty + j * 8) * Eq + n0 + tx];
        __syncthreads();
#pragma unroll
        for (int j = 0; j < 4; j++)
            o[(size_t)(n0 + ty + j * 8) * Fq + k0 + tx] = __float2half_rn(tile[tx][ty + j * 8]);
    }
}

// ---------------------------------------------------------------------------
// GEMM via single-pass fp16 mma.sync: P[z][4096,512] = X @ W, fp16 out.
// CTA tile 128x128, 8 warps (2x4), warp tile 64x32, K-chunk 32,
// double-buffered cp.async. grid (4, 32, 2), 256 thr.
// ---------------------------------------------------------------------------
#define KC 32
#define LDE 40
#define TILE_B (128 * LDE * 2)
#define BUF_B (2 * TILE_B)
#define GEMM_SMEM (2 * BUF_B)        // 40960

__global__ __launch_bounds__(256, 2) void gemm_tc_kernel()
{
    extern __shared__ char smem[];
    const uint32_t sbase = smem_u32(smem);
    const int tid = threadIdx.x;
    const int wid = tid >> 5;
    const int lane = tid & 31;
    const int z = blockIdx.z;
    const int rowBase = blockIdx.y * 128;
    const int colBase = blockIdx.x * 128;

    const __half* X = g_x16[z];
    const __half* W = g_w16[z];
    __half* C = g_P[z];

    const int wm = (wid >> 2) * 64;
    const int wn = (wid & 3) * 32;

    const int r0a = tid >> 2, s0 = (tid & 3) * 8;
    const int r1a = (tid + 256) >> 2;

    float acc[4][4][4];
#pragma unroll
    for (int mt = 0; mt < 4; mt++)
#pragma unroll
        for (int nt = 0; nt < 4; nt++)
#pragma unroll
            for (int i = 0; i < 4; i++) acc[mt][nt][i] = 0.f;

    auto stage = [&](int buf, int kt) {
        const uint32_t sb = sbase + buf * BUF_B;
#pragma unroll
        for (int t = 0; t < 2; t++) {
            const int row = t ? r1a : r0a;
            const uint32_t so = (uint32_t)(row * LDE + s0) * 2;
            cpasync16(sb + so,          X + (size_t)(rowBase + row) * Fq + kt + s0);
            cpasync16(sb + TILE_B + so, W + (size_t)(colBase + row) * Fq + kt + s0);
        }
        asm volatile("cp.async.commit_group;");
    };

    const int lj = lane >> 3, lr = lane & 7;
    const int arow = (lj & 1) * 8 + lr;
    const int acol = (lj >> 1) * 8;
    const int brow = (lj >> 1) * 8 + lr;
    const int bcol = (lj & 1) * 8;

    stage(0, 0);

    const int NCHUNK = Fq / KC;               // 16
    for (int c = 0; c < NCHUNK; c++) {
        if (c + 1 < NCHUNK) stage((c + 1) & 1, (c + 1) * KC);
        if (c + 1 < NCHUNK) asm volatile("cp.async.wait_group 1;");
        else                asm volatile("cp.async.wait_group 0;");
        __syncthreads();

        const uint32_t sb = sbase + (c & 1) * BUF_B;
#pragma unroll
        for (int ks = 0; ks < 2; ks++) {
            const int kof = ks * 16;
            uint32_t a[4][4], bfr[2][4];
#pragma unroll
            for (int mt = 0; mt < 4; mt++)
                ldsm_x4(a[mt][0], a[mt][1], a[mt][2], a[mt][3],
                        sb + (uint32_t)((wm + mt * 16 + arow) * LDE + kof + acol) * 2);
#pragma unroll
            for (int np = 0; np < 2; np++)
                ldsm_x4(bfr[np][0], bfr[np][1], bfr[np][2], bfr[np][3],
                        sb + TILE_B + (uint32_t)((wn + np * 16 + brow) * LDE + kof + bcol) * 2);
#pragma unroll
            for (int mt = 0; mt < 4; mt++)
#pragma unroll
                for (int nt = 0; nt < 4; nt++)
                    mma_f16(acc[mt][nt], a[mt],
                            bfr[nt >> 1][(nt & 1) * 2], bfr[nt >> 1][(nt & 1) * 2 + 1]);
        }
        __syncthreads();
    }

    // epilogue: fp16 stores (half traffic). thread t: rows g,g+8; cols 2*(t%4)
    const int g = lane >> 2, tg = lane & 3;
#pragma unroll
    for (int mt = 0; mt < 4; mt++)
#pragma unroll
        for (int nt = 0; nt < 4; nt++) {
            const int row = rowBase + wm + mt * 16 + g;
            const int col = colBase + wn + nt * 8 + 2 * tg;
            *(__half2*)(C + (size_t)row * Eq + col) =
                __floats2half2_rn(acc[mt][nt][0], acc[mt][nt][1]);
            *(__half2*)(C + (size_t)(row + 8) * Eq + col) =
                __floats2half2_rn(acc[mt][nt][2], acc[mt][nt][3]);
        }
}

// ---------------------------------------------------------------------------
// Fused epilogue v4: one CTA (256 thr) per TWO tokens.
// Warps 0-3 -> token 0, warps 4-7 -> token 1. In each 4-warp group:
//   all warps: content for 8 rows (m = g mod 4), fp16 Q x fp16 K,
//              contiguous uint4 loads (4 wavefronts each), red8 per 256-chunk
//   warps g=0..2: proj rows {2g, 2g+1} (fp32 Wl/v, fp16 Q as uint2)
//   warp  g=3:    kb (own K row)
// Head maps: content e=c*256+l*8+j -> h=4c+(l>>3); proj e=c*128+l*4+j -> h=2c+(l>>4)
// ---------------------------------------------------------------------------
__global__ __launch_bounds__(256) void fuse_kernel(
    const float* __restrict__ pl,     // (B,N,M,P)
    const int*   __restrict__ nbhd,   // (B,N,M)
    const float* __restrict__ Wl,     // (P,E)
    const float* __restrict__ u,      // 512 contiguous
    const float* __restrict__ v,      // 512 contiguous
    float*       __restrict__ out)    // (B,N,M,H)
{
    __shared__ float proj[2][Pq][Hq];
    __shared__ float kb[2][Hq];
    __shared__ float cont[2][Mq][Hq];

    const int tid = threadIdx.x;
    const int w = tid >> 5;
    const int l = tid & 31;
    const int t = w >> 2;             // token within CTA
    const int g = w & 3;              // warp within group
    const int tok = blockIdx.x * 2 + t;   // 0..4095
    const int b = tok >> 11;

    const __half* Qh = g_P[0] + (size_t)tok * Eq;
    const __half* Khb = g_P[1] + (size_t)b * Nq * Eq;
    const int* nbp = nbhd + (size_t)tok * Mq;

    // ---- content Q slice: 2 contiguous uint4 of halves ----
    float q16[16];
#pragma unroll
    for (int c = 0; c < 2; c++) {
        uint4 qv = *(const uint4*)(Qh + c * 256 + l * 8);
        h8_to_f(qv, q16 + c * 8);
    }

    // ---- content: 8 rows per warp (m = g + 4*jj), batched 4 rows ----
#pragma unroll
    for (int jb = 0; jb < 2; jb++) {
        uint4 kv[4][2];
        int mr[4];
#pragma unroll
        for (int i = 0; i < 4; i++) {
            mr[i] = g + 4 * (jb * 4 + i);
            const __half* Kp = Khb + (size_t)nbp[mr[i]] * Eq;
            kv[i][0] = *(const uint4*)(Kp + l * 8);
            kv[i][1] = *(const uint4*)(Kp + 256 + l * 8);
        }
#pragma unroll
        for (int i = 0; i < 4; i++) {
#pragma unroll
            for (int c = 0; c < 2; c++) {
                float kf[8];
                h8_to_f(kv[i][c], kf);
                float s = 0.f;
#pragma unroll
                for (int j = 0; j < 8; j++) s = fmaf(kf[j], q16[c * 8 + j], s);
                s = red8(s);
                if ((l & 7) == 0) cont[t][mr[i]][c * 4 + (l >> 3)] = s;
            }
        }
    }

    // ---- proj (warps g=0..2: rows 2g, 2g+1) / kb (warp g=3) ----
    if (g < 3) {
        const int hsub = l >> 4;
#pragma unroll
        for (int pi = 0; pi < 2; pi++) {
            const int pr = g * 2 + pi;
            const float* wlr = Wl + pr * Eq;
            float psum[4];
#pragma unroll
            for (int c = 0; c < 4; c++) {
                uint2 qp = *(const uint2*)(Qh + c * 128 + l * 4);
                float2 q0 = __half22float2(*(const __half2*)&qp.x);
                float2 q1 = __half22float2(*(const __half2*)&qp.y);
                float4 wv = *(const float4*)(wlr + c * 128 + l * 4);
                float4 vf = *(const float4*)(v + c * 128 + l * 4);
                float s = 0.f;
                s = fmaf(wv.x, q0.x + vf.x, s);
                s = fmaf(wv.y, q0.y + vf.y, s);
                s = fmaf(wv.z, q1.x + vf.z, s);
                s = fmaf(wv.w, q1.y + vf.w, s);
                psum[c] = red16(s);
            }
            if ((l & 15) == 0) {
#pragma unroll
                for (int c = 0; c < 4; c++) proj[t][pr][2 * c + hsub] = psum[c];
            }
        }
    } else {
        const __half* Kg = g_P[1] + (size_t)tok * Eq;
#pragma unroll
        for (int c = 0; c < 2; c++) {
            uint4 kk = *(const uint4*)(Kg + c * 256 + l * 8);
            float kf[8];
            h8_to_f(kk, kf);
            float4 u0 = *(const float4*)(u + c * 256 + l * 8);
            float4 u1 = *(const float4*)(u + c * 256 + l * 8 + 4);
            float s = 0.f;
            s = fmaf(kf[0], u0.x, s); s = fmaf(kf[1], u0.y, s);
            s = fmaf(kf[2], u0.z, s); s = fmaf(kf[3], u0.w, s);
            s = fmaf(kf[4], u1.x, s); s = fmaf(kf[5], u1.y, s);
            s = fmaf(kf[6], u1.z, s); s = fmaf(kf[7], u1.w, s);
            s = red8(s);
            if ((l & 7) == 0) kb[t][c * 4 + (l >> 3)] = s;
        }
    }
    __syncthreads();

    // ---- combine: 128 threads per token, 2 outputs each ----
    const int tt = tid >> 7;
    const int rest = tid & 127;
    const int m = rest >> 2;
    const int h0 = (rest & 3) * 2;
    const int tko = blockIdx.x * 2 + tt;
    const float* plp = pl + ((size_t)tko * Mq + m) * Pq;
    float plr[Pq];
#pragma unroll
    for (int pp = 0; pp < Pq; pp++) plr[pp] = plp[pp];

    float p0 = 0.f, p1 = 0.f;
#pragma unroll
    for (int pp = 0; pp < Pq; pp++) {
        p0 = fmaf(plr[pp], proj[tt][pp][h0], p0);
        p1 = fmaf(plr[pp], proj[tt][pp][h0 + 1], p1);
    }
    float* op = out + ((size_t)tko * Mq + m) * Hq + h0;
    op[0] = (cont[tt][m][h0] + p0 + kb[tt][h0]) * 0.125f;
    op[1] = (cont[tt][m][h0 + 1] + p1 + kb[tt][h0 + 1]) * 0.125f;
}

// ---------------------------------------------------------------------------
// Launch
// Inputs: 0 pairwise_locations, 1 mask (unused), 2 query_features,
// 3 key_features, 4 nbhd_idx, 5 Wq, 6 Wk, 7 Wl, 8 u, 9 v
// ---------------------------------------------------------------------------
extern "C" void kernel_launch(void* const* d_in, const int* in_sizes, int n_in,
                              void* d_out, int out_size)
{
    const float* pl   = (const float*)d_in[0];
    const float* qf   = (const float*)d_in[2];
    const float* kf   = (const float*)d_in[3];
    const int*   nb   = (const int*)  d_in[4];
    const float* Wq_  = (const float*)d_in[5];
    const float* Wk_  = (const float*)d_in[6];
    const float* Wl   = (const float*)d_in[7];
    const float* u    = (const float*)d_in[8];
    const float* v    = (const float*)d_in[9];
    float*       out  = (float*)d_out;

    static int smem_set = 0;
    if (!smem_set) {
        cudaFuncSetAttribute(gemm_tc_kernel,
                             cudaFuncAttributeMaxDynamicSharedMemorySize, GEMM_SMEM);
        smem_set = 1;
    }

    prep_kernel<<<dim3(1280, 1, 2), 256>>>(qf, kf, Wq_, Wk_);
    gemm_tc_kernel<<<dim3(4, 32, 2), 256, GEMM_SMEM>>>();
    fuse_kernel<<<Bq * Nq / 2, 256>>>(pl, nb, Wl, u, v, out);
}